// round 9
// baseline (speedup 1.0000x reference)
#include <cuda_runtime.h>

#define B_SZ 32
#define S_LEN 2048
#define D_MODEL 1024
#define NSTATE 256
#define LN_EPS 1e-5f

#define N_CHUNK 64           // 2048/32 timesteps per chunk
#define CHUNK_T 32
#define N_WORKER_BLK 116
#define N_WORKER_WARP (N_WORKER_BLK * 8)
#define GRID_TOTAL (B_SZ + N_WORKER_BLK)

__device__ float g_u[B_SZ * S_LEN];
__device__ float g_s[B_SZ * S_LEN];
__device__ int   g_ucnt[N_CHUNK];   // rows of u completed per t-chunk (target 1024)
__device__ int   g_swm[B_SZ];       // per-batch scan watermark (timesteps flushed)

__device__ __forceinline__ float warp_sum(float v) {
    #pragma unroll
    for (int o = 16; o; o >>= 1) v += __shfl_xor_sync(0xffffffffu, v, o);
    return v;
}
__device__ __forceinline__ int ld_acq(const int* p) {
    int v; asm volatile("ld.acquire.gpu.global.b32 %0,[%1];" : "=r"(v) : "l"(p)); return v;
}
__device__ __forceinline__ void st_rel(int* p, int v) {
    asm volatile("st.release.gpu.global.b32 [%0],%1;" :: "l"(p), "r"(v) : "memory");
}

__global__ void init_kernel() {
    int t = threadIdx.x;
    if (t < N_CHUNK) g_ucnt[t] = 0;
    if (t < B_SZ) g_swm[t] = 0;
}

__global__ void __launch_bounds__(256, 1) fused_kernel(
    const float* __restrict__ x,
    const float* __restrict__ llr,
    const float* __restrict__ logb,
    const float* __restrict__ cvec,
    const float* __restrict__ logd,
    const float* __restrict__ logstep,
    const float* __restrict__ alpha,
    const float* __restrict__ lngamma,
    const float* __restrict__ lnbeta,
    float* __restrict__ out)
{
    const int bid  = blockIdx.x;
    const int wid  = threadIdx.x >> 5;
    const int lane = threadIdx.x & 31;

    if (bid < B_SZ) {
        // ─────────────── scanner block: warp 0 only, batch b = bid ───────────────
        if (wid != 0) return;
        const int b = bid;

        const float step = expf(logstep[0]);
        float A[8], AB[8], BD[8], GC[8], QGC[8], QAB[8], QBD[8], z[8];
        float pgc=0.f, pbc=0.f, pca=0.f, pca2=0.f, pgca=0.f, pcab=0.f, pcbd=0.f,
              pgcab=0.f, pgcbd=0.f, pcaab=0.f, pcabd=0.f, pab2=0.f, pabbd=0.f, pbd2=0.f;
        #pragma unroll
        for (int j = 0; j < 8; j++) {
            int i = lane + 32 * j;
            float lam = -expf(llr[i]);
            float ad  = (2.0f + step * lam) / (2.0f - step * lam);
            float bb  = expf(logb[i]);
            float bd  = step * (1.0f + ad) * bb * 0.5f;
            float g   = lngamma[i];
            float be  = lnbeta[i];
            float cc  = cvec[i];
            float a   = ad * g;
            float ab  = ad * be;
            float gc  = g * cc;
            A[j]=a; AB[j]=ab; BD[j]=bd; GC[j]=gc;
            QGC[j]=gc*a; QAB[j]=a*ab; QBD[j]=a*bd;
            pgc  += gc;        pbc  += be*cc;
            pca  += a;         pca2 += a*a;      pgca += gc*a;
            pcab += ab;        pcbd += bd;
            pgcab+= gc*ab;     pgcbd+= gc*bd;
            pcaab+= a*ab;      pcabd+= a*bd;
            pab2 += ab*ab;     pabbd+= ab*bd;    pbd2 += bd*bd;
        }
        const float Sgc   = warp_sum(pgc);
        const float Sbc   = warp_sum(pbc);
        const float Ca    = warp_sum(pca);
        const float Ca2   = warp_sum(pca2);
        const float Cgca  = warp_sum(pgca);
        const float Cab   = warp_sum(pcab);
        const float Cbd   = warp_sum(pcbd);
        const float Cgcab = warp_sum(pgcab);
        const float Cgcbd = warp_sum(pgcbd);
        const float Caab  = warp_sum(pcaab);
        const float Cabd  = warp_sum(pcabd);
        const float Cab2  = warp_sum(pab2);
        const float Cabbd = warp_sum(pabbd);
        const float Cbd2  = warp_sum(pbd2);

        // wait for u chunk 0, load it (lane t holds u[b, c*32 + t])
        while (ld_acq(&g_ucnt[0]) < B_SZ * CHUNK_T) __nanosleep(100);
        float uc_cur = g_u[(size_t)b * S_LEN + lane];

        {
            float u0 = __shfl_sync(0xffffffffu, uc_cur, 0);
            #pragma unroll
            for (int j = 0; j < 8; j++) z[j] = BD[j] * u0;   // h0 = 0
        }

        const float invn = 1.0f / (float)NSTATE;
        for (int c = 0; c < N_CHUNK; c++) {
            // prefetch next chunk (gated; steady-state instant)
            float uc_next = 0.0f;
            if (c + 1 < N_CHUNK) {
                while (ld_acq(&g_ucnt[c + 1]) < B_SZ * CHUNK_T) __nanosleep(100);
                uc_next = g_u[(size_t)b * S_LEN + (c + 1) * CHUNK_T + lane];
            }

            float sc = 0.0f;   // per-lane s accumulator: lane t%32 gets s[c*32+t]
            #pragma unroll
            for (int g = 0; g < 16; g++) {
                // u[t+1], u[t+2] broadcasts
                float u1 = __shfl_sync(0xffffffffu, uc_cur, 2 * g + 1);
                float u2 = (g == 15) ? __shfl_sync(0xffffffffu, uc_next, 0)
                                     : __shfl_sync(0xffffffffu, uc_cur, 2 * g + 2);

                // ── 9-channel lane-local partials over z_t ──
                float q[8], m[8];
                float p0=0,p1=0,p2=0,p3=0,p4=0,p5=0,p6=0,p7=0,p8=0;
                #pragma unroll
                for (int j = 0; j < 8; j++) {
                    float zz = z[j];
                    float az = A[j] * zz;
                    p0 += zz;
                    p1 = fmaf(zz, zz, p1);
                    p2 = fmaf(GC[j], zz, p2);
                    p3 += az;
                    p4 = fmaf(A[j], az, p4);
                    p5 = fmaf(az, az, p5);
                    p6 = fmaf(QGC[j], zz, p6);
                    p7 = fmaf(QAB[j], zz, p7);
                    p8 = fmaf(QBD[j], zz, p8);
                }
                (void)q; (void)m;

                // ── one butterfly for all 9 channels ──
                #pragma unroll
                for (int o = 16; o; o >>= 1) {
                    p0 += __shfl_xor_sync(0xffffffffu, p0, o);
                    p1 += __shfl_xor_sync(0xffffffffu, p1, o);
                    p2 += __shfl_xor_sync(0xffffffffu, p2, o);
                    p3 += __shfl_xor_sync(0xffffffffu, p3, o);
                    p4 += __shfl_xor_sync(0xffffffffu, p4, o);
                    p5 += __shfl_xor_sync(0xffffffffu, p5, o);
                    p6 += __shfl_xor_sync(0xffffffffu, p6, o);
                    p7 += __shfl_xor_sync(0xffffffffu, p7, o);
                    p8 += __shfl_xor_sync(0xffffffffu, p8, o);
                }

                // ── step t scalars (direct) ──
                float mu  = p0 * invn;
                float var = fmaf(p1, invn, -mu * mu);
                float rs  = rsqrtf(var + LN_EPS);

                // ── step t+1 sums (analytic) ──
                float T2  = fmaf(mu * mu, Ca2, fmaf(-2.0f * mu, p4, p5));
                float T1  = fmaf(u1, p8, p7) - mu * fmaf(u1, Cabd, Caab);
                float T0  = fmaf(u1 * u1, Cbd2, fmaf(2.0f * u1, Cabbd, Cab2));
                float S1n = fmaf(rs, fmaf(-mu, Ca, p3), fmaf(Cbd, u1, Cab));
                float S3n = fmaf(rs, fmaf(-mu, Cgca, p6), fmaf(Cgcbd, u1, Cgcab));
                float S2n = fmaf(rs * rs, T2, fmaf(2.0f * rs, T1, T0));

                float mun  = S1n * invn;
                float varn = fmaf(S2n, invn, -mun * mun);
                float rsn  = rsqrtf(varn + LN_EPS);

                // readout (computed warp-uniform, SELed into the owning lane)
                float s0 = fmaf(rs,  fmaf(-mu,  Sgc, p2),  Sbc);
                float s1 = fmaf(rsn, fmaf(-mun, Sgc, S3n), Sbc);
                sc = (lane == 2 * g)     ? s0 : sc;
                sc = (lane == 2 * g + 1) ? s1 : sc;

                // ── advance z two steps (exact) ──
                float g1v = -rs * mu;
                float gnv = -rsn * mun;
                #pragma unroll
                for (int j = 0; j < 8; j++) {
                    float w  = fmaf(z[j], rs, g1v);
                    float z1 = fmaf(w, A[j], fmaf(BD[j], u1, AB[j]));
                    float w2 = fmaf(z1, rsn, gnv);
                    z[j]     = fmaf(w2, A[j], fmaf(BD[j], u2, AB[j]));
                }
            }

            // flush this chunk's s and publish watermark
            g_s[(size_t)b * S_LEN + c * CHUNK_T + lane] = sc;
            __threadfence();
            __syncwarp();
            if (lane == 0) st_rel(&g_swm[b], (c + 1) * CHUNK_T);

            uc_cur = uc_next;
        }
        return;
    }

    // ─────────────── worker block ───────────────
    const int wg = (bid - B_SZ) * 8 + wid;   // 0 .. 927

    // Phase 1: mean, t-major order (r = t*32 + b), chunk counters
    for (int r = wg; r < B_SZ * S_LEN; r += N_WORKER_WARP) {
        int t = r >> 5;
        int b = r & 31;
        const float4* xp = (const float4*)(x + ((size_t)b * S_LEN + t) * D_MODEL);
        float s = 0.f;
        #pragma unroll
        for (int k = 0; k < 8; k++) {
            float4 v = xp[lane + 32 * k];
            s += (v.x + v.y) + (v.z + v.w);
        }
        s = warp_sum(s);
        if (lane == 0) {
            g_u[(size_t)b * S_LEN + t] = s * (1.0f / (float)D_MODEL);
            __threadfence();
            atomicAdd(&g_ucnt[t >> 5], 1);
        }
    }

    // Phase 2: out, t-major order, gated on per-batch watermarks
    float a_sig = 1.0f / (1.0f + expf(-alpha[0]));
    float dd = expf(logd[0]);
    float c1 = a_sig + (1.0f - a_sig) * dd;
    float c2 = 1.0f - a_sig;

    for (int r = wg; r < B_SZ * S_LEN; r += N_WORKER_WARP) {
        int t = r >> 5;
        int b = r & 31;
        while (ld_acq(&g_swm[b]) <= t) __nanosleep(200);
        float c2s = c2 * g_s[(size_t)b * S_LEN + t];

        const float4* xp = (const float4*)(x + ((size_t)b * S_LEN + t) * D_MODEL);
        float4* op = (float4*)(out + ((size_t)b * S_LEN + t) * D_MODEL);
        #pragma unroll
        for (int k = 0; k < 8; k++) {
            float4 v = xp[lane + 32 * k];
            v.x = fmaf(c1, v.x, c2s);
            v.y = fmaf(c1, v.y, c2s);
            v.z = fmaf(c1, v.z, c2s);
            v.w = fmaf(c1, v.w, c2s);
            op[lane + 32 * k] = v;
        }
    }
}

extern "C" void kernel_launch(void* const* d_in, const int* in_sizes, int n_in,
                              void* d_out, int out_size) {
    const float* x        = (const float*)d_in[0];
    const float* llr      = (const float*)d_in[1];
    const float* logb     = (const float*)d_in[2];
    const float* cvec     = (const float*)d_in[3];
    const float* logd     = (const float*)d_in[4];
    const float* logstep  = (const float*)d_in[5];
    const float* alpha    = (const float*)d_in[6];
    const float* lngamma  = (const float*)d_in[7];
    const float* lnbeta   = (const float*)d_in[8];
    float* out = (float*)d_out;

    init_kernel<<<1, 256>>>();
    fused_kernel<<<GRID_TOTAL, 256>>>(x, llr, logb, cvec, logd, logstep,
                                      alpha, lngamma, lnbeta, out);
}